// round 8
// baseline (speedup 1.0000x reference)
#include <cuda_runtime.h>
#include <cuda_bf16.h>
#include <cstdint>

#define NN   32768
#define EE   524288
#define FIN  128
#define HH   256
#define NB   32
#define BN_EPS 1e-5f

typedef __nv_bfloat16 bf16;

// ---------------- scratch (device globals) ----------------
__device__ bf16  g_xcatH[NN * FIN];
__device__ bf16  g_xcatL[NN * FIN];
__device__ bf16  g_meanH[NN * HH];
__device__ bf16  g_meanL[NN * HH];
__device__ float g_lin  [NN * HH];
__device__ bf16  g_actH [NN * HH];
__device__ bf16  g_actL [NN * HH];
__device__ float g_y    [NB * HH];
__device__ int   g_deg   [NN];
__device__ int   g_rowptr[NN + 1];
__device__ int   g_cursor[NN];
__device__ int   g_csr   [EE];
__device__ float g_invdeg[NN];
__device__ float g_bnsum4[4 * HH];
__device__ float g_bnsq4 [4 * HH];
// transposed/split weights: [N=256 rows, K] bf16
__device__ bf16 g_Wl0T_h[HH * FIN], g_Wl0T_l[HH * FIN];
__device__ bf16 g_Wr0T_h[HH * FIN], g_Wr0T_l[HH * FIN];
__device__ bf16 g_WlT_h[3 * HH * HH], g_WlT_l[3 * HH * HH];
__device__ bf16 g_WrT_h[3 * HH * HH], g_WrT_l[3 * HH * HH];
__device__ bf16 g_W1aT_h[HH * 1024], g_W1aT_l[HH * 1024];

// ---------------- helpers ----------------
__device__ __forceinline__ uint32_t smem_u32(const void* p) {
    uint32_t a;
    asm("{ .reg .u64 t; cvta.to.shared.u64 t, %1; cvt.u32.u64 %0, t; }" : "=r"(a) : "l"(p));
    return a;
}
__device__ __forceinline__ uint32_t pack2(bf16 a, bf16 b) {
    return (uint32_t)__bfloat16_as_ushort(a) | ((uint32_t)__bfloat16_as_ushort(b) << 16);
}
__device__ __forceinline__ void split2(float v, bf16& h, bf16& l) {
    h = __float2bfloat16_rn(v);
    l = __float2bfloat16_rn(v - __bfloat162float(h));
}
__device__ __forceinline__ float2 unpk(uint32_t u) {
    __nv_bfloat162 b = *reinterpret_cast<__nv_bfloat162*>(&u);
    return __bfloat1622float2(b);
}
__device__ __forceinline__ void ldsm4(uint32_t* r, uint32_t addr) {
    asm volatile("ldmatrix.sync.aligned.m8n8.x4.shared.b16 {%0,%1,%2,%3}, [%4];"
                 : "=r"(r[0]), "=r"(r[1]), "=r"(r[2]), "=r"(r[3]) : "r"(addr));
}
__device__ __forceinline__ void mma16816(float* c, const uint32_t* a, const uint32_t* b) {
    asm volatile(
        "mma.sync.aligned.m16n8k16.row.col.f32.bf16.bf16.f32 "
        "{%0,%1,%2,%3}, {%4,%5,%6,%7}, {%8,%9}, {%0,%1,%2,%3};"
        : "+f"(c[0]), "+f"(c[1]), "+f"(c[2]), "+f"(c[3])
        : "r"(a[0]), "r"(a[1]), "r"(a[2]), "r"(a[3]), "r"(b[0]), "r"(b[1]));
}
#define CPASYNC(s, g) asm volatile("cp.async.cg.shared.global [%0], [%1], 16;" :: "r"(s), "l"(g))
#define CPCOMMIT()    asm volatile("cp.async.commit_group;" ::: "memory")
#define CPWAIT(n)     asm volatile("cp.async.wait_group %0;" :: "n"(n) : "memory")

// ---------------- fused prep ----------------
// [0,16384): concat->bf16 h/l; [16384,19200): weights; [19200,19328): deg zero;
// [19328,19336): bn zero; [19336,19368): y zero
__global__ __launch_bounds__(256) void k_prep(
    const float* __restrict__ x_ori, const float* __restrict__ g0,
    const float* __restrict__ g1, const float* __restrict__ g2,
    const float* __restrict__ Wl0, const float* __restrict__ Wr0,
    const float* __restrict__ Wl, const float* __restrict__ Wr,
    const float* __restrict__ W1a) {
    int b = blockIdx.x;
    int t = threadIdx.x;
    if (b < 16384) {
        int idx = b * 256 + t;
        int n = idx >> 7, f = idx & 127;
        float v;
        if (f < 32)       v = x_ori[n * 32 + f];
        else if (f < 64)  v = g0[n * 32 + (f - 32)];
        else if (f < 96)  v = g1[n * 32 + (f - 64)];
        else              v = g2[n * 32 + (f - 96)];
        bf16 h, l; split2(v, h, l);
        g_xcatH[idx] = h;
        g_xcatL[idx] = l;
    } else if (b < 19200) {
        int wb = b - 16384;
        const float* W; bf16 *Th, *Tl; int K, base;
        if (wb < 128)        { W = Wl0; Th = g_Wl0T_h; Tl = g_Wl0T_l; K = 128;  base = wb; }
        else if (wb < 256)   { W = Wr0; Th = g_Wr0T_h; Tl = g_Wr0T_l; K = 128;  base = wb - 128; }
        else if (wb < 1024)  { int i = (wb - 256) >> 8;
                               W = Wl + i * 65536; Th = g_WlT_h + i * 65536; Tl = g_WlT_l + i * 65536;
                               K = 256; base = (wb - 256) & 255; }
        else if (wb < 1792)  { int i = (wb - 1024) >> 8;
                               W = Wr + i * 65536; Th = g_WrT_h + i * 65536; Tl = g_WrT_l + i * 65536;
                               K = 256; base = (wb - 1024) & 255; }
        else                 { W = W1a; Th = g_W1aT_h; Tl = g_W1aT_l; K = 1024; base = wb - 1792; }
        int idx = base * 256 + t;
        int k = idx >> 8, n = idx & 255;
        float v = W[idx];
        bf16 h, l; split2(v, h, l);
        Th[n * K + k] = h;
        Tl[n * K + k] = l;
    } else if (b < 19328) {
        g_deg[(b - 19200) * 256 + t] = 0;
    } else if (b < 19336) {
        int i = (b - 19328) * 256 + t;
        if (i < 4 * HH) { g_bnsum4[i] = 0.f; g_bnsq4[i] = 0.f; }
    } else {
        g_y[(b - 19336) * 256 + t] = 0.f;
    }
}

// ---------------- CSR build ----------------
__global__ void k_count(const int* __restrict__ ei) {
    int e = blockIdx.x * 256 + threadIdx.x;
    if (e < EE) atomicAdd(&g_deg[ei[e]], 1);
}
__global__ __launch_bounds__(1024) void k_scan() {
    __shared__ int part[1024];
    int t = threadIdx.x;
    const int4* dp = (const int4*)g_deg;
    int s = 0;
    for (int i = 0; i < 8; i++) {
        int4 v = dp[t * 8 + i];
        s += v.x + v.y + v.z + v.w;
    }
    part[t] = s;
    __syncthreads();
    for (int off = 1; off < 1024; off <<= 1) {
        int tmp = (t >= off) ? part[t - off] : 0;
        __syncthreads();
        part[t] += tmp;
        __syncthreads();
    }
    int run = part[t] - s;
    for (int i = 0; i < 8; i++) {
        int4 v = dp[t * 8 + i];
        int d0 = v.x, d1 = v.y, d2 = v.z, d3 = v.w;
        int4 r4;
        r4.x = run; run += d0;
        r4.y = run; run += d1;
        r4.z = run; run += d2;
        r4.w = run; run += d3;
        ((int4*)g_rowptr)[t * 8 + i] = r4;
        ((int4*)g_cursor)[t * 8 + i] = r4;
        float4 iv;
        iv.x = d0 > 0 ? 1.0f / (float)d0 : 0.0f;
        iv.y = d1 > 0 ? 1.0f / (float)d1 : 0.0f;
        iv.z = d2 > 0 ? 1.0f / (float)d2 : 0.0f;
        iv.w = d3 > 0 ? 1.0f / (float)d3 : 0.0f;
        ((float4*)g_invdeg)[t * 8 + i] = iv;
    }
    if (t == 1023) g_rowptr[NN] = part[1023];
}
__global__ void k_fill(const int* __restrict__ ei) {
    int e = blockIdx.x * 256 + threadIdx.x;
    if (e < EE) {
        int d = ei[e];
        int s = ei[EE + e];
        int pos = atomicAdd(&g_cursor[d], 1);
        g_csr[pos] = s;
    }
}

// ---------------- mean aggregation: reads bf16 (h,l) pairs, writes bf16 h/l ----------------
template <int F>
__global__ __launch_bounds__(256) void k_agg(const bf16* __restrict__ xh, const bf16* __restrict__ xl,
                                             bf16* __restrict__ oh, bf16* __restrict__ ol) {
    int n = blockIdx.x * 8 + (threadIdx.x >> 5);
    if (n >= NN) return;
    int lane = threadIdx.x & 31;
    constexpr int C = F / 32;          // bf16 per lane (4 or 8)
    int s = g_rowptr[n], e = g_rowptr[n + 1];
    float acc[C];
#pragma unroll
    for (int j = 0; j < C; j++) acc[j] = 0.f;

    auto addrow = [&](int src) {
        if (F == 256) {
            uint4 h4 = ((const uint4*)(xh + (size_t)src * F))[lane];
            uint4 l4 = ((const uint4*)(xl + (size_t)src * F))[lane];
            float2 p;
            p = unpk(h4.x); acc[0] += p.x; acc[1] += p.y;
            p = unpk(h4.y); acc[2] += p.x; acc[3] += p.y;
            p = unpk(h4.z); acc[4] += p.x; acc[5] += p.y;
            p = unpk(h4.w); acc[6] += p.x; acc[7] += p.y;
            p = unpk(l4.x); acc[0] += p.x; acc[1] += p.y;
            p = unpk(l4.y); acc[2] += p.x; acc[3] += p.y;
            p = unpk(l4.z); acc[4] += p.x; acc[5] += p.y;
            p = unpk(l4.w); acc[6] += p.x; acc[7] += p.y;
        } else {
            uint2 h2 = ((const uint2*)(xh + (size_t)src * F))[lane];
            uint2 l2 = ((const uint2*)(xl + (size_t)src * F))[lane];
            float2 p;
            p = unpk(h2.x); acc[0] += p.x; acc[1] += p.y;
            p = unpk(h2.y); acc[2] += p.x; acc[3] += p.y;
            p = unpk(l2.x); acc[0] += p.x; acc[1] += p.y;
            p = unpk(l2.y); acc[2] += p.x; acc[3] += p.y;
        }
    };

    int i = s;
    for (; i + 4 <= e; i += 4) {
        int s0 = g_csr[i], s1 = g_csr[i + 1], s2 = g_csr[i + 2], s3 = g_csr[i + 3];
        addrow(s0); addrow(s1); addrow(s2); addrow(s3);
    }
    for (; i < e; i++) addrow(g_csr[i]);

    float id = g_invdeg[n];
    uint32_t uh[C / 2], ul[C / 2];
#pragma unroll
    for (int j = 0; j < C; j += 2) {
        float v0 = acc[j] * id, v1 = acc[j + 1] * id;
        bf16 h0, l0, h1, l1;
        split2(v0, h0, l0); split2(v1, h1, l1);
        uh[j / 2] = pack2(h0, h1);
        ul[j / 2] = pack2(l0, l1);
    }
    if (F == 256) {
        ((uint4*)(oh + (size_t)n * F))[lane] = *(uint4*)uh;
        ((uint4*)(ol + (size_t)n * F))[lane] = *(uint4*)ul;
    } else {
        ((uint2*)(oh + (size_t)n * F))[lane] = *(uint2*)uh;
        ((uint2*)(ol + (size_t)n * F))[lane] = *(uint2*)ul;
    }
}

// ---------------- mma.sync bf16 GEMM over segments ----------------
// Block tile 128x256, warp tile 64x64 (2x4 warps), BK=64, 2-stage cp.async.
// C[M,256] = sum_s segA[s] @ segB[s]^T + bias, optional relu.
// bnsum!=null: fused per-column sum/sumsq atomics.
// wvec!=null: skip C store; yout[row] += relu(C)·wvec.
struct Segs { const bf16* a[6]; const bf16* b[6]; };

#define STAGE_BYTES 49152
#define GSMEM_BYTES (2 * STAGE_BYTES)

__global__ __launch_bounds__(256, 1) void k_gemm(
    Segs segs, int nseg, int K, const float* __restrict__ bias,
    float* __restrict__ C, int relu,
    float* __restrict__ bnsum, float* __restrict__ bnsq,
    const float* __restrict__ wvec, float* __restrict__ yout) {
    extern __shared__ __align__(128) char smem[];
    uint32_t sb = smem_u32(smem);
    int tid = threadIdx.x;
    int L = tid & 31, w = tid >> 5;
    int wm = w & 1, wn = w >> 1;               // 2 x 4 warps
    int cps = K >> 6;
    int nit = nseg * cps;
    size_t arow0 = (size_t)blockIdx.x * 128;

    auto stage = [&](int it) {
        int s = it / cps, c = it - s * cps;
        const char* A = (const char*)(segs.a[s] + arow0 * K);
        const char* B = (const char*)segs.b[s];
        uint32_t sa = sb + (uint32_t)(it & 1) * STAGE_BYTES;
        uint32_t sbB = sa + 16384u;
        int row = tid >> 3, ch = tid & 7;
        size_t koff = (size_t)c * 128 + (size_t)ch * 16;
#pragma unroll
        for (int i = 0; i < 4; i++) {
            int r = row + i * 32;
            uint32_t so = sa + r * 128 + ((ch ^ (r & 7)) << 4);
            CPASYNC(so, A + (size_t)r * K * 2 + koff);
        }
#pragma unroll
        for (int i = 0; i < 8; i++) {
            int r = row + i * 32;
            uint32_t so = sbB + r * 128 + ((ch ^ (r & 7)) << 4);
            CPASYNC(so, B + (size_t)r * K * 2 + koff);
        }
    };

    float acc[4][8][4];
#pragma unroll
    for (int mt = 0; mt < 4; mt++)
#pragma unroll
        for (int nt = 0; nt < 8; nt++)
#pragma unroll
            for (int q = 0; q < 4; q++) acc[mt][nt][q] = 0.f;

    int rowA[4], rowB[4];
#pragma unroll
    for (int mt = 0; mt < 4; mt++) rowA[mt] = wm * 64 + mt * 16 + ((L >> 3) & 1) * 8 + (L & 7);
#pragma unroll
    for (int bt = 0; bt < 4; bt++) rowB[bt] = wn * 64 + bt * 16 + (L >> 4) * 8 + (L & 7);
    int chA = (L >> 4);
    int chB = (L >> 3) & 1;

    stage(0); CPCOMMIT();
    for (int it = 0; it < nit; it++) {
        if (it + 1 < nit) { stage(it + 1); CPCOMMIT(); CPWAIT(1); }
        else              { CPWAIT(0); }
        __syncthreads();
        uint32_t sa = sb + (uint32_t)(it & 1) * STAGE_BYTES;
        uint32_t sbB = sa + 16384u;
#pragma unroll
        for (int ks = 0; ks < 4; ks++) {
            uint32_t af[4][4], bfr[4][4];
#pragma unroll
            for (int mt = 0; mt < 4; mt++) {
                int r = rowA[mt];
                int ch = 2 * ks + chA;
                ldsm4(af[mt], sa + r * 128 + ((ch ^ (r & 7)) << 4));
            }
#pragma unroll
            for (int bt = 0; bt < 4; bt++) {
                int r = rowB[bt];
                int ch = 2 * ks + chB;
                ldsm4(bfr[bt], sbB + r * 128 + ((ch ^ (r & 7)) << 4));
            }
#pragma unroll
            for (int mt = 0; mt < 4; mt++)
#pragma unroll
                for (int nt = 0; nt < 8; nt++)
                    mma16816(acc[mt][nt], af[mt], &bfr[nt >> 1][(nt & 1) * 2]);
        }
        __syncthreads();
    }

    // epilogue
    int colbase = wn * 64;
    float cs[16], cq[16], ps[8];
#pragma unroll
    for (int j = 0; j < 16; j++) { cs[j] = 0.f; cq[j] = 0.f; }
#pragma unroll
    for (int j = 0; j < 8; j++) ps[j] = 0.f;
#pragma unroll
    for (int mt = 0; mt < 4; mt++) {
        size_t r0 = arow0 + wm * 64 + mt * 16 + (L >> 2);
        float* C0 = C + r0 * 256;
        float* C1 = C + (r0 + 8) * 256;
#pragma unroll
        for (int nt = 0; nt < 8; nt++) {
            int col = colbase + nt * 8 + (L & 3) * 2;
            float2 bv = *(const float2*)(bias + col);
            float2 v0, v1;
            v0.x = acc[mt][nt][0] + bv.x; v0.y = acc[mt][nt][1] + bv.y;
            v1.x = acc[mt][nt][2] + bv.x; v1.y = acc[mt][nt][3] + bv.y;
            if (bnsum) {
                cs[2 * nt + 0] += v0.x + v1.x;
                cs[2 * nt + 1] += v0.y + v1.y;
                cq[2 * nt + 0] += v0.x * v0.x + v1.x * v1.x;
                cq[2 * nt + 1] += v0.y * v0.y + v1.y * v1.y;
            }
            if (relu) {
                v0.x = fmaxf(v0.x, 0.f); v0.y = fmaxf(v0.y, 0.f);
                v1.x = fmaxf(v1.x, 0.f); v1.y = fmaxf(v1.y, 0.f);
            }
            if (wvec) {
                float2 wv = *(const float2*)(wvec + col);
                ps[mt * 2 + 0] += v0.x * wv.x + v0.y * wv.y;
                ps[mt * 2 + 1] += v1.x * wv.x + v1.y * wv.y;
            } else {
                *(float2*)(C0 + col) = v0;
                *(float2*)(C1 + col) = v1;
            }
        }
    }
    if (bnsum) {
#pragma unroll
        for (int j = 0; j < 16; j++) {
#pragma unroll
            for (int off = 4; off <= 16; off <<= 1) {
                cs[j] += __shfl_xor_sync(0xFFFFFFFFu, cs[j], off);
                cq[j] += __shfl_xor_sync(0xFFFFFFFFu, cq[j], off);
            }
        }
        if (L < 4) {
#pragma unroll
            for (int nt = 0; nt < 8; nt++) {
                int col = colbase + nt * 8 + L * 2;
                atomicAdd(&bnsum[col + 0], cs[2 * nt + 0]);
                atomicAdd(&bnsum[col + 1], cs[2 * nt + 1]);
                atomicAdd(&bnsq [col + 0], cq[2 * nt + 0]);
                atomicAdd(&bnsq [col + 1], cq[2 * nt + 1]);
            }
        }
    }
    if (wvec) {
#pragma unroll
        for (int j = 0; j < 8; j++) {
            ps[j] += __shfl_xor_sync(0xFFFFFFFFu, ps[j], 1);
            ps[j] += __shfl_xor_sync(0xFFFFFFFFu, ps[j], 2);
        }
        if ((L & 3) == 0) {
#pragma unroll
            for (int mt = 0; mt < 4; mt++) {
                size_t r0 = arow0 + wm * 64 + mt * 16 + (L >> 2);
                atomicAdd(&yout[r0], ps[mt * 2 + 0]);
                atomicAdd(&yout[r0 + 8], ps[mt * 2 + 1]);
            }
        }
    }
}

// ---------------- BatchNorm finalize+apply (fused) -> bf16 h/l only ----------------
__global__ __launch_bounds__(256) void k_bnapply(
    const float4* __restrict__ C,
    bf16* __restrict__ oh, bf16* __restrict__ ol,
    const float* __restrict__ gamma, const float* __restrict__ beta,
    const float* __restrict__ bnsum, const float* __restrict__ bnsq) {
    __shared__ float ssc[HH], ssh[HH];
    int t = threadIdx.x;
    {
        const float invN = 1.0f / (float)NN;
        float m = bnsum[t] * invN;
        float var = bnsq[t] * invN - m * m;
        float sc = gamma[t] * rsqrtf(var + BN_EPS);
        ssc[t] = sc;
        ssh[t] = beta[t] - m * sc;
    }
    __syncthreads();
    int idx = blockIdx.x * 256 + t;                 // over NN*64
    if (idx >= NN * (HH / 4)) return;
    int c4 = (idx & 63) * 4;
    float4 v = C[idx];
    v.x = fmaxf(v.x * ssc[c4 + 0] + ssh[c4 + 0], 0.f);
    v.y = fmaxf(v.y * ssc[c4 + 1] + ssh[c4 + 1], 0.f);
    v.z = fmaxf(v.z * ssc[c4 + 2] + ssh[c4 + 2], 0.f);
    v.w = fmaxf(v.w * ssc[c4 + 3] + ssh[c4 + 3], 0.f);
    bf16 hx, lx, hy, ly, hz, lz, hw, lw;
    split2(v.x, hx, lx); split2(v.y, hy, ly);
    split2(v.z, hz, lz); split2(v.w, hw, lw);
    uint2 uh, ul;
    uh.x = pack2(hx, hy); uh.y = pack2(hz, hw);
    ul.x = pack2(lx, ly); ul.y = pack2(lz, lw);
    size_t e = (size_t)idx * 4;
    *(uint2*)(oh + e) = uh;
    *(uint2*)(ol + e) = ul;
}

// ---------------- fused tail: final BN (32 rows) + mlp2 ----------------
__global__ __launch_bounds__(256) void k_bnmlp2(
    const float* __restrict__ gamma, const float* __restrict__ beta,
    const float* __restrict__ b1b,
    const float* __restrict__ W2a, const float* __restrict__ b2a,
    const float* __restrict__ W2b, const float* __restrict__ b2b,
    float* __restrict__ out) {
    int b = blockIdx.x;
    int t = threadIdx.x;
    __shared__ float xs[HH], hs[HH];
    float b1 = b1b[0];
    float s = 0.f, q = 0.f;
    for (int r = 0; r < NB; r++) {
        float v = g_y[r * HH + t] + b1;
        s += v;
        q += v * v;
    }
    float m = s / (float)NB;
    float var = q / (float)NB - m * m;
    float sc = gamma[t] * rsqrtf(var + BN_EPS);
    float sh = beta[t] - m * sc;
    float yv = g_y[b * HH + t] + b1;
    xs[t] = fmaxf(yv * sc + sh, 0.f);
    __syncthreads();
    float acc = b2a[t];
    for (int k = 0; k < HH; k++) acc += xs[k] * W2a[k * HH + t];
    hs[t] = fmaxf(acc, 0.f);
    __syncthreads();
    if (t < 16) {
        float o = b2b[t];
        for (int k = 0; k < HH; k++) o += hs[k] * W2b[k * 16 + t];
        out[b * 16 + t] = o;
    }
}

// ---------------- host side ----------------
#define SYM(var, sym) { void* p_; cudaGetSymbolAddress(&p_, sym); var = decltype(var)(p_); }

extern "C" void kernel_launch(void* const* d_in, const int* in_sizes, int n_in,
                              void* d_out, int out_size) {
    const float* x_ori = (const float*)d_in[0];
    const float* g0    = (const float*)d_in[1];
    const float* g1    = (const float*)d_in[2];
    const float* g2    = (const float*)d_in[3];
    const int* ei      = (const int*)d_in[4];
    const float* Wl0 = (const float*)d_in[5];
    const float* Wr0 = (const float*)d_in[6];
    const float* bb0 = (const float*)d_in[7];
    const float* Wl  = (const float*)d_in[8];
    const float* Wr  = (const float*)d_in[9];
    const float* bb  = (const float*)d_in[10];
    const float* gamma = (const float*)d_in[11];
    const float* beta  = (const float*)d_in[12];
    const float* W1a = (const float*)d_in[13];
    const float* b1a = (const float*)d_in[14];
    const float* W1b = (const float*)d_in[15];
    const float* b1b = (const float*)d_in[16];
    const float* gamma_f = (const float*)d_in[17];
    const float* beta_f  = (const float*)d_in[18];
    const float* W2a = (const float*)d_in[19];
    const float* b2a = (const float*)d_in[20];
    const float* W2b = (const float*)d_in[21];
    const float* b2b = (const float*)d_in[22];
    float* out = (float*)d_out;

    float *lin, *bnsum, *bnsq, *yv;
    bf16 *meanH, *meanL, *actH, *actL, *xcatH, *xcatL;
    bf16 *Wl0Th, *Wl0Tl, *Wr0Th, *Wr0Tl, *WlTh, *WlTl, *WrTh, *WrTl, *W1aTh, *W1aTl;
    SYM(lin, g_lin); SYM(yv, g_y);
    SYM(bnsum, g_bnsum4); SYM(bnsq, g_bnsq4);
    SYM(xcatH, g_xcatH); SYM(xcatL, g_xcatL);
    SYM(meanH, g_meanH); SYM(meanL, g_meanL);
    SYM(actH, g_actH); SYM(actL, g_actL);
    SYM(Wl0Th, g_Wl0T_h); SYM(Wl0Tl, g_Wl0T_l);
    SYM(Wr0Th, g_Wr0T_h); SYM(Wr0Tl, g_Wr0T_l);
    SYM(WlTh, g_WlT_h); SYM(WlTl, g_WlT_l);
    SYM(WrTh, g_WrT_h); SYM(WrTl, g_WrT_l);
    SYM(W1aTh, g_W1aT_h); SYM(W1aTl, g_W1aT_l);

    cudaFuncSetAttribute(k_gemm, cudaFuncAttributeMaxDynamicSharedMemorySize, GSMEM_BYTES);

    // fused prep
    k_prep<<<19368, 256>>>(x_ori, g0, g1, g2, Wl0, Wr0, Wl, Wr, W1a);
    // CSR build
    k_count<<<EE / 256, 256>>>(ei);
    k_scan<<<1, 1024>>>();
    k_fill<<<EE / 256, 256>>>(ei);

    dim3 lgrid(NN / 128, 1);

    // ---- layer 0 (K=128, 6 segments) ----
    k_agg<FIN><<<NN / 8, 256>>>(xcatH, xcatL, meanH, meanL);
    {
        Segs s;
        s.a[0] = meanH; s.b[0] = Wl0Th;
        s.a[1] = meanH; s.b[1] = Wl0Tl;
        s.a[2] = meanL; s.b[2] = Wl0Th;
        s.a[3] = xcatH; s.b[3] = Wr0Th;
        s.a[4] = xcatH; s.b[4] = Wr0Tl;
        s.a[5] = xcatL; s.b[5] = Wr0Th;
        k_gemm<<<lgrid, 256, GSMEM_BYTES>>>(s, 6, FIN, bb0, lin, 0, bnsum, bnsq, nullptr, nullptr);
    }
    k_bnapply<<<NN * (HH / 4) / 256, 256>>>((const float4*)lin, actH, actL,
                                            gamma, beta, bnsum, bnsq);

    // ---- layers 1..3 (K=256) ----
    for (int i = 0; i < 3; i++) {
        k_agg<HH><<<NN / 8, 256>>>(actH, actL, meanH, meanL);
        bf16* wl_h = WlTh + (size_t)i * HH * HH;
        bf16* wl_l = WlTl + (size_t)i * HH * HH;
        bf16* wr_h = WrTh + (size_t)i * HH * HH;
        bf16* wr_l = WrTl + (size_t)i * HH * HH;
        Segs s;
        s.a[0] = meanH; s.b[0] = wl_h;
        s.a[1] = meanH; s.b[1] = wl_l;
        s.a[2] = meanL; s.b[2] = wl_h;
        s.a[3] = actH;  s.b[3] = wr_h;
        s.a[4] = actH;  s.b[4] = wr_l;
        s.a[5] = actL;  s.b[5] = wr_h;
        float* bs = bnsum + (size_t)(i + 1) * HH;
        float* bq = bnsq + (size_t)(i + 1) * HH;
        k_gemm<<<lgrid, 256, GSMEM_BYTES>>>(s, 6, HH, bb + (size_t)i * HH, lin, 0, bs, bq,
                                            nullptr, nullptr);
        k_bnapply<<<NN * (HH / 4) / 256, 256>>>((const float4*)lin, actH, actL,
                                                gamma + (size_t)(i + 1) * HH,
                                                beta + (size_t)(i + 1) * HH, bs, bq);
    }

    // ---- mlp1 (fused second stage): y += relu(X@W1a + b1a) · W1b ----
    {
        Segs s;
        s.a[0] = actH; s.b[0] = W1aTh;
        s.a[1] = actH; s.b[1] = W1aTl;
        s.a[2] = actL; s.b[2] = W1aTh;
        s.a[3] = actH; s.b[3] = W1aTh;   // unused
        s.a[4] = actH; s.b[4] = W1aTh;
        s.a[5] = actH; s.b[5] = W1aTh;
        dim3 mgrid(8192 / 128, 1);
        k_gemm<<<mgrid, 256, GSMEM_BYTES>>>(s, 3, 1024, b1a, lin, 1, nullptr, nullptr, W1b, yv);
    }
    // fused final BN + mlp2
    k_bnmlp2<<<NB, 256>>>(gamma_f, beta_f, b1b, W2a, b2a, W2b, b2b, out);

    (void)in_sizes; (void)n_in; (void)out_size;
}

// round 10
// speedup vs baseline: 1.0799x; 1.0799x over previous
#include <cuda_runtime.h>
#include <cuda_bf16.h>
#include <cstdint>

#define NN   32768
#define EE   524288
#define FIN  128
#define HH   256
#define NB   32
#define BN_EPS 1e-5f

typedef __nv_bfloat16 bf16;

// ---------------- scratch (device globals) ----------------
__device__ bf16  g_xcatH[NN * FIN];
__device__ bf16  g_xcatL[NN * FIN];
__device__ bf16  g_meanH[NN * HH];
__device__ bf16  g_meanL[NN * HH];
__device__ float g_lin  [NN * HH];
__device__ bf16  g_actH [NN * HH];
__device__ bf16  g_actL [NN * HH];
__device__ float g_y    [NB * HH];
__device__ int   g_deg   [NN];
__device__ int   g_rowptr[NN + 1];
__device__ int   g_cursor[NN];
__device__ int   g_csr   [EE];
__device__ float g_invdeg[NN];
__device__ float g_bnsum4[4 * HH];
__device__ float g_bnsq4 [4 * HH];
// transposed/split weights: [N=256 rows, K] bf16
__device__ bf16 g_Wl0T_h[HH * FIN], g_Wl0T_l[HH * FIN];
__device__ bf16 g_Wr0T_h[HH * FIN], g_Wr0T_l[HH * FIN];
__device__ bf16 g_WlT_h[3 * HH * HH], g_WlT_l[3 * HH * HH];
__device__ bf16 g_WrT_h[3 * HH * HH], g_WrT_l[3 * HH * HH];
__device__ bf16 g_W1aT_h[HH * 1024], g_W1aT_l[HH * 1024];

// ---------------- helpers ----------------
__device__ __forceinline__ uint32_t smem_u32(const void* p) {
    uint32_t a;
    asm("{ .reg .u64 t; cvta.to.shared.u64 t, %1; cvt.u32.u64 %0, t; }" : "=r"(a) : "l"(p));
    return a;
}
__device__ __forceinline__ uint32_t pack2(bf16 a, bf16 b) {
    return (uint32_t)__bfloat16_as_ushort(a) | ((uint32_t)__bfloat16_as_ushort(b) << 16);
}
__device__ __forceinline__ void split2(float v, bf16& h, bf16& l) {
    h = __float2bfloat16_rn(v);
    l = __float2bfloat16_rn(v - __bfloat162float(h));
}
__device__ __forceinline__ float2 unpk(uint32_t u) {
    __nv_bfloat162 b = *reinterpret_cast<__nv_bfloat162*>(&u);
    return __bfloat1622float2(b);
}
__device__ __forceinline__ void ldsm4(uint32_t* r, uint32_t addr) {
    asm volatile("ldmatrix.sync.aligned.m8n8.x4.shared.b16 {%0,%1,%2,%3}, [%4];"
                 : "=r"(r[0]), "=r"(r[1]), "=r"(r[2]), "=r"(r[3]) : "r"(addr));
}
__device__ __forceinline__ void mma16816(float* c, const uint32_t* a, const uint32_t* b) {
    asm volatile(
        "mma.sync.aligned.m16n8k16.row.col.f32.bf16.bf16.f32 "
        "{%0,%1,%2,%3}, {%4,%5,%6,%7}, {%8,%9}, {%0,%1,%2,%3};"
        : "+f"(c[0]), "+f"(c[1]), "+f"(c[2]), "+f"(c[3])
        : "r"(a[0]), "r"(a[1]), "r"(a[2]), "r"(a[3]), "r"(b[0]), "r"(b[1]));
}
#define CPASYNC(s, g) asm volatile("cp.async.cg.shared.global [%0], [%1], 16;" :: "r"(s), "l"(g))
#define CPCOMMIT()    asm volatile("cp.async.commit_group;" ::: "memory")
#define CPWAIT(n)     asm volatile("cp.async.wait_group %0;" :: "n"(n) : "memory")

// ---------------- fused prep ----------------
// [0,16384): concat->bf16 h/l; [16384,19200): weights; [19200,19328): deg zero;
// [19328,19336): bn zero; [19336,19368): y zero
__global__ __launch_bounds__(256) void k_prep(
    const float* __restrict__ x_ori, const float* __restrict__ g0,
    const float* __restrict__ g1, const float* __restrict__ g2,
    const float* __restrict__ Wl0, const float* __restrict__ Wr0,
    const float* __restrict__ Wl, const float* __restrict__ Wr,
    const float* __restrict__ W1a) {
    int b = blockIdx.x;
    int t = threadIdx.x;
    if (b < 16384) {
        int idx = b * 256 + t;
        int n = idx >> 7, f = idx & 127;
        float v;
        if (f < 32)       v = x_ori[n * 32 + f];
        else if (f < 64)  v = g0[n * 32 + (f - 32)];
        else if (f < 96)  v = g1[n * 32 + (f - 64)];
        else              v = g2[n * 32 + (f - 96)];
        bf16 h, l; split2(v, h, l);
        g_xcatH[idx] = h;
        g_xcatL[idx] = l;
    } else if (b < 19200) {
        int wb = b - 16384;
        const float* W; bf16 *Th, *Tl; int K, base;
        if (wb < 128)        { W = Wl0; Th = g_Wl0T_h; Tl = g_Wl0T_l; K = 128;  base = wb; }
        else if (wb < 256)   { W = Wr0; Th = g_Wr0T_h; Tl = g_Wr0T_l; K = 128;  base = wb - 128; }
        else if (wb < 1024)  { int i = (wb - 256) >> 8;
                               W = Wl + i * 65536; Th = g_WlT_h + i * 65536; Tl = g_WlT_l + i * 65536;
                               K = 256; base = (wb - 256) & 255; }
        else if (wb < 1792)  { int i = (wb - 1024) >> 8;
                               W = Wr + i * 65536; Th = g_WrT_h + i * 65536; Tl = g_WrT_l + i * 65536;
                               K = 256; base = (wb - 1024) & 255; }
        else                 { W = W1a; Th = g_W1aT_h; Tl = g_W1aT_l; K = 1024; base = wb - 1792; }
        int idx = base * 256 + t;
        int k = idx >> 8, n = idx & 255;
        float v = W[idx];
        bf16 h, l; split2(v, h, l);
        Th[n * K + k] = h;
        Tl[n * K + k] = l;
    } else if (b < 19328) {
        g_deg[(b - 19200) * 256 + t] = 0;
    } else if (b < 19336) {
        int i = (b - 19328) * 256 + t;
        if (i < 4 * HH) { g_bnsum4[i] = 0.f; g_bnsq4[i] = 0.f; }
    } else {
        g_y[(b - 19336) * 256 + t] = 0.f;
    }
}

// ---------------- CSR build ----------------
__global__ void k_count(const int* __restrict__ ei) {
    int e = blockIdx.x * 256 + threadIdx.x;
    if (e < EE) atomicAdd(&g_deg[ei[e]], 1);
}
__global__ __launch_bounds__(1024) void k_scan() {
    __shared__ int part[1024];
    int t = threadIdx.x;
    const int4* dp = (const int4*)g_deg;
    int s = 0;
    for (int i = 0; i < 8; i++) {
        int4 v = dp[t * 8 + i];
        s += v.x + v.y + v.z + v.w;
    }
    part[t] = s;
    __syncthreads();
    for (int off = 1; off < 1024; off <<= 1) {
        int tmp = (t >= off) ? part[t - off] : 0;
        __syncthreads();
        part[t] += tmp;
        __syncthreads();
    }
    int run = part[t] - s;
    for (int i = 0; i < 8; i++) {
        int4 v = dp[t * 8 + i];
        int d0 = v.x, d1 = v.y, d2 = v.z, d3 = v.w;
        int4 r4;
        r4.x = run; run += d0;
        r4.y = run; run += d1;
        r4.z = run; run += d2;
        r4.w = run; run += d3;
        ((int4*)g_rowptr)[t * 8 + i] = r4;
        ((int4*)g_cursor)[t * 8 + i] = r4;
        float4 iv;
        iv.x = d0 > 0 ? 1.0f / (float)d0 : 0.0f;
        iv.y = d1 > 0 ? 1.0f / (float)d1 : 0.0f;
        iv.z = d2 > 0 ? 1.0f / (float)d2 : 0.0f;
        iv.w = d3 > 0 ? 1.0f / (float)d3 : 0.0f;
        ((float4*)g_invdeg)[t * 8 + i] = iv;
    }
    if (t == 1023) g_rowptr[NN] = part[1023];
}
__global__ void k_fill(const int* __restrict__ ei) {
    int e = blockIdx.x * 256 + threadIdx.x;
    if (e < EE) {
        int d = ei[e];
        int s = ei[EE + e];
        int pos = atomicAdd(&g_cursor[d], 1);
        g_csr[pos] = s;
    }
}

// ---------------- mean aggregation: reads bf16 (h,l) pairs, writes bf16 h/l ----------------
template <int F>
__global__ __launch_bounds__(256) void k_agg(const bf16* __restrict__ xh, const bf16* __restrict__ xl,
                                             bf16* __restrict__ oh, bf16* __restrict__ ol) {
    int n = blockIdx.x * 8 + (threadIdx.x >> 5);
    if (n >= NN) return;
    int lane = threadIdx.x & 31;
    constexpr int C = F / 32;          // bf16 per lane (4 or 8)
    int s = g_rowptr[n], e = g_rowptr[n + 1];
    float acc[C];
#pragma unroll
    for (int j = 0; j < C; j++) acc[j] = 0.f;

    auto addrow = [&](int src) {
        if (F == 256) {
            uint4 h4 = ((const uint4*)(xh + (size_t)src * F))[lane];
            uint4 l4 = ((const uint4*)(xl + (size_t)src * F))[lane];
            float2 p;
            p = unpk(h4.x); acc[0] += p.x; acc[1] += p.y;
            p = unpk(h4.y); acc[2] += p.x; acc[3] += p.y;
            p = unpk(h4.z); acc[4] += p.x; acc[5] += p.y;
            p = unpk(h4.w); acc[6] += p.x; acc[7] += p.y;
            p = unpk(l4.x); acc[0] += p.x; acc[1] += p.y;
            p = unpk(l4.y); acc[2] += p.x; acc[3] += p.y;
            p = unpk(l4.z); acc[4] += p.x; acc[5] += p.y;
            p = unpk(l4.w); acc[6] += p.x; acc[7] += p.y;
        } else {
            uint2 h2 = ((const uint2*)(xh + (size_t)src * F))[lane];
            uint2 l2 = ((const uint2*)(xl + (size_t)src * F))[lane];
            float2 p;
            p = unpk(h2.x); acc[0] += p.x; acc[1] += p.y;
            p = unpk(h2.y); acc[2] += p.x; acc[3] += p.y;
            p = unpk(l2.x); acc[0] += p.x; acc[1] += p.y;
            p = unpk(l2.y); acc[2] += p.x; acc[3] += p.y;
        }
    };

    int i = s;
    for (; i + 4 <= e; i += 4) {
        int s0 = g_csr[i], s1 = g_csr[i + 1], s2 = g_csr[i + 2], s3 = g_csr[i + 3];
        addrow(s0); addrow(s1); addrow(s2); addrow(s3);
    }
    for (; i < e; i++) addrow(g_csr[i]);

    float id = g_invdeg[n];
    uint32_t uh[C / 2], ul[C / 2];
#pragma unroll
    for (int j = 0; j < C; j += 2) {
        float v0 = acc[j] * id, v1 = acc[j + 1] * id;
        bf16 h0, l0, h1, l1;
        split2(v0, h0, l0); split2(v1, h1, l1);
        uh[j / 2] = pack2(h0, h1);
        ul[j / 2] = pack2(l0, l1);
    }
    if (F == 256) {
        ((uint4*)(oh + (size_t)n * F))[lane] = *(uint4*)uh;
        ((uint4*)(ol + (size_t)n * F))[lane] = *(uint4*)ul;
    } else {
        ((uint2*)(oh + (size_t)n * F))[lane] = *(uint2*)uh;
        ((uint2*)(ol + (size_t)n * F))[lane] = *(uint2*)ul;
    }
}

// ---------------- mma.sync bf16 GEMM over segments (round-7 config) ----------------
// Block tile 128x128 (grid.y=2 covers N=256), warp tile 32x64, BK=64, 3-stage.
// C[M,256] = sum_s segA[s] @ segB[s]^T + bias, optional relu.
// bnsum!=null: fused per-column sum/sumsq atomics.
// wvec!=null: skip C store; yout[row] += relu(C)·wvec.
struct Segs { const bf16* a[6]; const bf16* b[6]; };

#define GSMEM_BYTES 98304

__global__ __launch_bounds__(256, 2) void k_gemm(
    Segs segs, int nseg, int K, const float* __restrict__ bias,
    float* __restrict__ C, int relu,
    float* __restrict__ bnsum, float* __restrict__ bnsq,
    const float* __restrict__ wvec, float* __restrict__ yout) {
    extern __shared__ __align__(128) char smem[];
    uint32_t sb = smem_u32(smem);
    int tid = threadIdx.x;
    int L = tid & 31, w = tid >> 5;
    int wm = w & 3, wn = w >> 2;
    int cps = K >> 6;
    int nit = nseg * cps;
    size_t arow0 = (size_t)blockIdx.x * 128;
    size_t brow0 = (size_t)blockIdx.y * 128;

    auto stage = [&](int it) {
        int s = it / cps, c = it - s * cps;
        const char* A = (const char*)(segs.a[s] + arow0 * K);
        const char* B = (const char*)(segs.b[s] + brow0 * K);
        uint32_t sa = sb + (uint32_t)(it % 3) * 32768u;
        uint32_t sbB = sa + 16384u;
        int row = tid >> 3, ch = tid & 7;
        size_t koff = (size_t)c * 128 + (size_t)ch * 16;
#pragma unroll
        for (int i = 0; i < 4; i++) {
            int r = row + i * 32;
            uint32_t so = sa + r * 128 + ((ch ^ (r & 7)) << 4);
            CPASYNC(so, A + (size_t)r * K * 2 + koff);
        }
#pragma unroll
        for (int i = 0; i < 4; i++) {
            int r = row + i * 32;
            uint32_t so = sbB + r * 128 + ((ch ^ (r & 7)) << 4);
            CPASYNC(so, B + (size_t)r * K * 2 + koff);
        }
    };

    float acc[2][8][4];
#pragma unroll
    for (int mt = 0; mt < 2; mt++)
#pragma unroll
        for (int nt = 0; nt < 8; nt++)
#pragma unroll
            for (int q = 0; q < 4; q++) acc[mt][nt][q] = 0.f;

    int rowA[2], rowB[4];
#pragma unroll
    for (int mt = 0; mt < 2; mt++) rowA[mt] = wm * 32 + mt * 16 + ((L >> 3) & 1) * 8 + (L & 7);
#pragma unroll
    for (int bt = 0; bt < 4; bt++) rowB[bt] = wn * 64 + bt * 16 + (L >> 4) * 8 + (L & 7);
    int chA = (L >> 4);
    int chB = (L >> 3) & 1;

    stage(0); CPCOMMIT();
    if (nit > 1) { stage(1); CPCOMMIT(); }
    for (int it = 0; it < nit; it++) {
        if (it + 2 < nit) { stage(it + 2); CPCOMMIT(); CPWAIT(2); }
        else if (it + 1 < nit) { CPWAIT(1); }
        else { CPWAIT(0); }
        __syncthreads();
        uint32_t sa = sb + (uint32_t)(it % 3) * 32768u;
        uint32_t sbB = sa + 16384u;
#pragma unroll
        for (int ks = 0; ks < 4; ks++) {
            uint32_t af[2][4], bfr[4][4];
#pragma unroll
            for (int mt = 0; mt < 2; mt++) {
                int r = rowA[mt];
                int ch = 2 * ks + chA;
                ldsm4(af[mt], sa + r * 128 + ((ch ^ (r & 7)) << 4));
            }
#pragma unroll
            for (int bt = 0; bt < 4; bt++) {
                int r = rowB[bt];
                int ch = 2 * ks + chB;
                ldsm4(bfr[bt], sbB + r * 128 + ((ch ^ (r & 7)) << 4));
            }
#pragma unroll
            for (int mt = 0; mt < 2; mt++)
#pragma unroll
                for (int nt = 0; nt < 8; nt++)
                    mma16816(acc[mt][nt], af[mt], &bfr[nt >> 1][(nt & 1) * 2]);
        }
        __syncthreads();
    }

    // epilogue
    int colbase = (int)brow0 + wn * 64;
    float cs[16], cq[16], ps[4];
#pragma unroll
    for (int j = 0; j < 16; j++) { cs[j] = 0.f; cq[j] = 0.f; }
#pragma unroll
    for (int j = 0; j < 4; j++) ps[j] = 0.f;
#pragma unroll
    for (int mt = 0; mt < 2; mt++) {
        size_t r0 = arow0 + wm * 32 + mt * 16 + (L >> 2);
        float* C0 = C + r0 * 256;
        float* C1 = C + (r0 + 8) * 256;
#pragma unroll
        for (int nt = 0; nt < 8; nt++) {
            int col = colbase + nt * 8 + (L & 3) * 2;
            float2 bv = *(const float2*)(bias + col);
            float2 v0, v1;
            v0.x = acc[mt][nt][0] + bv.x; v0.y = acc[mt][nt][1] + bv.y;
            v1.x = acc[mt][nt][2] + bv.x; v1.y = acc[mt][nt][3] + bv.y;
            if (bnsum) {
                cs[2 * nt + 0] += v0.x + v1.x;
                cs[2 * nt + 1] += v0.y + v1.y;
                cq[2 * nt + 0] += v0.x * v0.x + v1.x * v1.x;
                cq[2 * nt + 1] += v0.y * v0.y + v1.y * v1.y;
            }
            if (relu) {
                v0.x = fmaxf(v0.x, 0.f); v0.y = fmaxf(v0.y, 0.f);
                v1.x = fmaxf(v1.x, 0.f); v1.y = fmaxf(v1.y, 0.f);
            }
            if (wvec) {
                float2 wv = *(const float2*)(wvec + col);
                ps[mt * 2 + 0] += v0.x * wv.x + v0.y * wv.y;
                ps[mt * 2 + 1] += v1.x * wv.x + v1.y * wv.y;
            } else {
                *(float2*)(C0 + col) = v0;
                *(float2*)(C1 + col) = v1;
            }
        }
    }
    if (bnsum) {
#pragma unroll
        for (int j = 0; j < 16; j++) {
#pragma unroll
            for (int off = 4; off <= 16; off <<= 1) {
                cs[j] += __shfl_xor_sync(0xFFFFFFFFu, cs[j], off);
                cq[j] += __shfl_xor_sync(0xFFFFFFFFu, cq[j], off);
            }
        }
        if (L < 4) {
#pragma unroll
            for (int nt = 0; nt < 8; nt++) {
                int col = colbase + nt * 8 + L * 2;
                atomicAdd(&bnsum[col + 0], cs[2 * nt + 0]);
                atomicAdd(&bnsum[col + 1], cs[2 * nt + 1]);
                atomicAdd(&bnsq [col + 0], cq[2 * nt + 0]);
                atomicAdd(&bnsq [col + 1], cq[2 * nt + 1]);
            }
        }
    }
    if (wvec) {
#pragma unroll
        for (int j = 0; j < 4; j++) {
            ps[j] += __shfl_xor_sync(0xFFFFFFFFu, ps[j], 1);
            ps[j] += __shfl_xor_sync(0xFFFFFFFFu, ps[j], 2);
        }
        if ((L & 3) == 0) {
#pragma unroll
            for (int mt = 0; mt < 2; mt++) {
                size_t r0 = arow0 + wm * 32 + mt * 16 + (L >> 2);
                atomicAdd(&yout[r0], ps[mt * 2 + 0]);
                atomicAdd(&yout[r0 + 8], ps[mt * 2 + 1]);
            }
        }
    }
}

// ---------------- BatchNorm finalize+apply (fused) -> bf16 h/l only ----------------
__global__ __launch_bounds__(256) void k_bnapply(
    const float4* __restrict__ C,
    bf16* __restrict__ oh, bf16* __restrict__ ol,
    const float* __restrict__ gamma, const float* __restrict__ beta,
    const float* __restrict__ bnsum, const float* __restrict__ bnsq) {
    __shared__ float ssc[HH], ssh[HH];
    int t = threadIdx.x;
    {
        const float invN = 1.0f / (float)NN;
        float m = bnsum[t] * invN;
        float var = bnsq[t] * invN - m * m;
        float sc = gamma[t] * rsqrtf(var + BN_EPS);
        ssc[t] = sc;
        ssh[t] = beta[t] - m * sc;
    }
    __syncthreads();
    int idx = blockIdx.x * 256 + t;                 // over NN*64
    if (idx >= NN * (HH / 4)) return;
    int c4 = (idx & 63) * 4;
    float4 v = C[idx];
    v.x = fmaxf(v.x * ssc[c4 + 0] + ssh[c4 + 0], 0.f);
    v.y = fmaxf(v.y * ssc[c4 + 1] + ssh[c4 + 1], 0.f);
    v.z = fmaxf(v.z * ssc[c4 + 2] + ssh[c4 + 2], 0.f);
    v.w = fmaxf(v.w * ssc[c4 + 3] + ssh[c4 + 3], 0.f);
    bf16 hx, lx, hy, ly, hz, lz, hw, lw;
    split2(v.x, hx, lx); split2(v.y, hy, ly);
    split2(v.z, hz, lz); split2(v.w, hw, lw);
    uint2 uh, ul;
    uh.x = pack2(hx, hy); uh.y = pack2(hz, hw);
    ul.x = pack2(lx, ly); ul.y = pack2(lz, lw);
    size_t e = (size_t)idx * 4;
    *(uint2*)(oh + e) = uh;
    *(uint2*)(ol + e) = ul;
}

// ---------------- fused tail: final BN (32 rows) + mlp2 ----------------
__global__ __launch_bounds__(256) void k_bnmlp2(
    const float* __restrict__ gamma, const float* __restrict__ beta,
    const float* __restrict__ b1b,
    const float* __restrict__ W2a, const float* __restrict__ b2a,
    const float* __restrict__ W2b, const float* __restrict__ b2b,
    float* __restrict__ out) {
    int b = blockIdx.x;
    int t = threadIdx.x;
    __shared__ float xs[HH], hs[HH];
    float b1 = b1b[0];
    float s = 0.f, q = 0.f;
    for (int r = 0; r < NB; r++) {
        float v = g_y[r * HH + t] + b1;
        s += v;
        q += v * v;
    }
    float m = s / (float)NB;
    float var = q / (float)NB - m * m;
    float sc = gamma[t] * rsqrtf(var + BN_EPS);
    float sh = beta[t] - m * sc;
    float yv = g_y[b * HH + t] + b1;
    xs[t] = fmaxf(yv * sc + sh, 0.f);
    __syncthreads();
    float acc = b2a[t];
    for (int k = 0; k < HH; k++) acc += xs[k] * W2a[k * HH + t];
    hs[t] = fmaxf(acc, 0.f);
    __syncthreads();
    if (t < 16) {
        float o = b2b[t];
        for (int k = 0; k < HH; k++) o += hs[k] * W2b[k * 16 + t];
        out[b * 16 + t] = o;
    }
}

// ---------------- host side ----------------
#define SYM(var, sym) { void* p_; cudaGetSymbolAddress(&p_, sym); var = decltype(var)(p_); }

extern "C" void kernel_launch(void* const* d_in, const int* in_sizes, int n_in,
                              void* d_out, int out_size) {
    const float* x_ori = (const float*)d_in[0];
    const float* g0    = (const float*)d_in[1];
    const float* g1    = (const float*)d_in[2];
    const float* g2    = (const float*)d_in[3];
    const int* ei      = (const int*)d_in[4];
    const float* Wl0 = (const float*)d_in[5];
    const float* Wr0 = (const float*)d_in[6];
    const float* bb0 = (const float*)d_in[7];
    const float* Wl  = (const float*)d_in[8];
    const float* Wr  = (const float*)d_in[9];
    const float* bb  = (const float*)d_in[10];
    const float* gamma = (const float*)d_in[11];
    const float* beta  = (const float*)d_in[12];
    const float* W1a = (const float*)d_in[13];
    const float* b1a = (const float*)d_in[14];
    const float* W1b = (const float*)d_in[15];
    const float* b1b = (const float*)d_in[16];
    const float* gamma_f = (const float*)d_in[17];
    const float* beta_f  = (const float*)d_in[18];
    const float* W2a = (const float*)d_in[19];
    const float* b2a = (const float*)d_in[20];
    const float* W2b = (const float*)d_in[21];
    const float* b2b = (const float*)d_in[22];
    float* out = (float*)d_out;

    float *lin, *bnsum, *bnsq, *yv;
    bf16 *meanH, *meanL, *actH, *actL, *xcatH, *xcatL;
    bf16 *Wl0Th, *Wl0Tl, *Wr0Th, *Wr0Tl, *WlTh, *WlTl, *WrTh, *WrTl, *W1aTh, *W1aTl;
    SYM(lin, g_lin); SYM(yv, g_y);
    SYM(bnsum, g_bnsum4); SYM(bnsq, g_bnsq4);
    SYM(xcatH, g_xcatH); SYM(xcatL, g_xcatL);
    SYM(meanH, g_meanH); SYM(meanL, g_meanL);
    SYM(actH, g_actH); SYM(actL, g_actL);
    SYM(Wl0Th, g_Wl0T_h); SYM(Wl0Tl, g_Wl0T_l);
    SYM(Wr0Th, g_Wr0T_h); SYM(Wr0Tl, g_Wr0T_l);
    SYM(WlTh, g_WlT_h); SYM(WlTl, g_WlT_l);
    SYM(WrTh, g_WrT_h); SYM(WrTl, g_WrT_l);
    SYM(W1aTh, g_W1aT_h); SYM(W1aTl, g_W1aT_l);

    cudaFuncSetAttribute(k_gemm, cudaFuncAttributeMaxDynamicSharedMemorySize, GSMEM_BYTES);

    // fused prep
    k_prep<<<19368, 256>>>(x_ori, g0, g1, g2, Wl0, Wr0, Wl, Wr, W1a);
    // CSR build
    k_count<<<EE / 256, 256>>>(ei);
    k_scan<<<1, 1024>>>();
    k_fill<<<EE / 256, 256>>>(ei);

    dim3 lgrid(NN / 128, 2);

    // ---- layer 0 (K=128, 6 segments) ----
    k_agg<FIN><<<NN / 8, 256>>>(xcatH, xcatL, meanH, meanL);
    {
        Segs s;
        s.a[0] = meanH; s.b[0] = Wl0Th;
        s.a[1] = meanH; s.b[1] = Wl0Tl;
        s.a[2] = meanL; s.b[2] = Wl0Th;
        s.a[3] = xcatH; s.b[3] = Wr0Th;
        s.a[4] = xcatH; s.b[4] = Wr0Tl;
        s.a[5] = xcatL; s.b[5] = Wr0Th;
        k_gemm<<<lgrid, 256, GSMEM_BYTES>>>(s, 6, FIN, bb0, lin, 0, bnsum, bnsq, nullptr, nullptr);
    }
    k_bnapply<<<NN * (HH / 4) / 256, 256>>>((const float4*)lin, actH, actL,
                                            gamma, beta, bnsum, bnsq);

    // ---- layers 1..3 (K=256) ----
    for (int i = 0; i < 3; i++) {
        k_agg<HH><<<NN / 8, 256>>>(actH, actL, meanH, meanL);
        bf16* wl_h = WlTh + (size_t)i * HH * HH;
        bf16* wl_l = WlTl + (size_t)i * HH * HH;
        bf16* wr_h = WrTh + (size_t)i * HH * HH;
        bf16* wr_l = WrTl + (size_t)i * HH * HH;
        Segs s;
        s.a[0] = meanH; s.b[0] = wl_h;
        s.a[1] = meanH; s.b[1] = wl_l;
        s.a[2] = meanL; s.b[2] = wl_h;
        s.a[3] = actH;  s.b[3] = wr_h;
        s.a[4] = actH;  s.b[4] = wr_l;
        s.a[5] = actL;  s.b[5] = wr_h;
        float* bs = bnsum + (size_t)(i + 1) * HH;
        float* bq = bnsq + (size_t)(i + 1) * HH;
        k_gemm<<<lgrid, 256, GSMEM_BYTES>>>(s, 6, HH, bb + (size_t)i * HH, lin, 0, bs, bq,
                                            nullptr, nullptr);
        k_bnapply<<<NN * (HH / 4) / 256, 256>>>((const float4*)lin, actH, actL,
                                                gamma + (size_t)(i + 1) * HH,
                                                beta + (size_t)(i + 1) * HH, bs, bq);
    }

    // ---- mlp1 (fused second stage): y += relu(X@W1a + b1a) · W1b ----
    {
        Segs s;
        s.a[0] = actH; s.b[0] = W1aTh;
        s.a[1] = actH; s.b[1] = W1aTl;
        s.a[2] = actL; s.b[2] = W1aTh;
        s.a[3] = actH; s.b[3] = W1aTh;   // unused
        s.a[4] = actH; s.b[4] = W1aTh;
        s.a[5] = actH; s.b[5] = W1aTh;
        dim3 mgrid(8192 / 128, 2);
        k_gemm<<<mgrid, 256, GSMEM_BYTES>>>(s, 3, 1024, b1a, lin, 1, nullptr, nullptr, W1b, yv);
    }
    // fused final BN + mlp2
    k_bnmlp2<<<NB, 256>>>(gamma_f, beta_f, b1b, W2a, b2a, W2b, b2b, out);

    (void)in_sizes; (void)n_in; (void)out_size;
}